// round 8
// baseline (speedup 1.0000x reference)
#include <cuda_runtime.h>
#include <cuda_bf16.h>
#include <math.h>

#define BDIM 512
#define DDIM 512
#define CDIM 100000
#define SCALE_F 64.0f
#define MARGIN_F 0.35f

#define TILE_N 128
#define NT 782                         // ceil(100000/128)
#define C_PAD (NT * TILE_N)            // padded W rows (zero-filled)
#define NPART (NT * 4)                 // per-row partials (4 warp-columns per tile)
#define GRIDX 37                       // 37*4 = 148 CTAs = 1 wave

#define NSTAGE 4
#define AQ_STRIDE 528                  // A smem row stride bytes (512 + 16)
#define BQ_STRIDE 80                   // B smem row stride bytes (64 + 16)
#define A_SMEM_BYTES (128 * AQ_STRIDE)            // 67584
#define B_STAGE_BYTES (128 * BQ_STRIDE)           // 10240
#define SMEM_DYN (A_SMEM_BYTES + NSTAGE * B_STAGE_BYTES)  // 108544

// ---------------- device scratch ----------------
__device__ uint4  g_xq4[BDIM * 32];                 // x quantized int8 (packed)
__device__ float  g_xn[BDIM * DDIM];                // normalized x fp32 (for cosgt)
__device__ float  g_sx[BDIM];                       // x row scales
__device__ uint4  g_wq4[(size_t)C_PAD * 32];        // W quantized int8 (~51 MB)
__device__ float  g_sw[C_PAD];                      // W row scales (0 on padding)
__device__ float  g_pm[BDIM * NPART];
__device__ float  g_ps[BDIM * NPART];
__device__ float  g_cosgt[BDIM];
__device__ float  g_nll[BDIM];
__device__ int    g_is64;

// ---------------- helpers ----------------
__device__ __forceinline__ unsigned smem_u32(const void* p) {
    unsigned a;
    asm("{ .reg .u64 t; cvta.to.shared.u64 t, %1; cvt.u32.u64 %0, t; }" : "=r"(a) : "l"(p));
    return a;
}
#define CP_ASYNC16(d, s) asm volatile("cp.async.cg.shared.global [%0], [%1], 16;" :: "r"(d), "l"(s) : "memory")
#define CP_COMMIT()  asm volatile("cp.async.commit_group;" ::: "memory")
#define CP_WAIT2()   asm volatile("cp.async.wait_group 2;" ::: "memory")

__device__ __forceinline__ unsigned pack_s8(float a, float b, float c, float d, float inv_s) {
    int q0 = __float2int_rn(a * inv_s) & 0xFF;
    int q1 = __float2int_rn(b * inv_s) & 0xFF;
    int q2 = __float2int_rn(c * inv_s) & 0xFF;
    int q3 = __float2int_rn(d * inv_s);
    return (unsigned)(q0 | (q1 << 8) | (q2 << 16) | (q3 << 24));
}

// frag load, one k32 step (byte offset ksB within 64B chunk rows)
__device__ __forceinline__ void load_frags8(
    unsigned sbA, unsigned bB, int aRow, int aColB, int bRow, int bColB,
    int ksB, unsigned (*a)[4], unsigned (*bf)[2])
{
    #pragma unroll
    for (int i = 0; i < 2; i++) {
        unsigned addr = sbA + (aRow + i * 16) * AQ_STRIDE + ksB + aColB;
        asm volatile("ldmatrix.sync.aligned.m8n8.x4.shared.b16 {%0,%1,%2,%3}, [%4];"
                     : "=r"(a[i][0]), "=r"(a[i][1]), "=r"(a[i][2]), "=r"(a[i][3])
                     : "r"(addr));
    }
    #pragma unroll
    for (int j2 = 0; j2 < 2; j2++) {
        unsigned addr = bB + (bRow + j2 * 16) * BQ_STRIDE + ksB + bColB;
        unsigned r0, r1, r2, r3;
        asm volatile("ldmatrix.sync.aligned.m8n8.x4.shared.b16 {%0,%1,%2,%3}, [%4];"
                     : "=r"(r0), "=r"(r1), "=r"(r2), "=r"(r3) : "r"(addr));
        bf[j2 * 2 + 0][0] = r0; bf[j2 * 2 + 0][1] = r1;
        bf[j2 * 2 + 1][0] = r2; bf[j2 * 2 + 1][1] = r3;
    }
}

// ---------------- small kernels ----------------
__global__ void detect_gt_kernel(const int* __restrict__ graw) {
    __shared__ int any_nz;
    if (threadIdx.x == 0) any_nz = 0;
    __syncthreads();
    if ((threadIdx.x & 1) && graw[threadIdx.x] != 0) any_nz = 1;
    __syncthreads();
    if (threadIdx.x == 0) g_is64 = any_nz ? 0 : 1;
}

__global__ void __launch_bounds__(128) norm_x_kernel(const float* __restrict__ x) {
    int b = blockIdx.x, tid = threadIdx.x;
    float4 v = ((const float4*)(x + (size_t)b * DDIM))[tid];
    float ss = v.x*v.x + v.y*v.y + v.z*v.z + v.w*v.w;
    #pragma unroll
    for (int o = 16; o; o >>= 1) ss += __shfl_xor_sync(0xffffffffu, ss, o);
    __shared__ float sm[4], sm2[4];
    if ((tid & 31) == 0) sm[tid >> 5] = ss;
    __syncthreads();
    float tot = sm[0] + sm[1] + sm[2] + sm[3];
    float r = 1.0f / fmaxf(sqrtf(tot), 1e-12f);
    float4 n = make_float4(v.x*r, v.y*r, v.z*r, v.w*r);
    ((float4*)(g_xn + (size_t)b * DDIM))[tid] = n;
    float mx = fmaxf(fmaxf(fabsf(n.x), fabsf(n.y)), fmaxf(fabsf(n.z), fabsf(n.w)));
    #pragma unroll
    for (int o = 16; o; o >>= 1) mx = fmaxf(mx, __shfl_xor_sync(0xffffffffu, mx, o));
    if ((tid & 31) == 0) sm2[tid >> 5] = mx;
    __syncthreads();
    mx = fmaxf(fmaxf(sm2[0], sm2[1]), fmaxf(sm2[2], sm2[3]));
    mx = fmaxf(mx, 1e-30f);
    float inv_s = 127.0f / mx;
    ((unsigned*)g_xq4)[b * 128 + tid] = pack_s8(n.x, n.y, n.z, n.w, inv_s);
    if (tid == 0) g_sx[b] = mx / 127.0f;
}

__global__ void __launch_bounds__(128) norm_w_kernel(const float* __restrict__ wt) {
    int c = blockIdx.x, tid = threadIdx.x;
    if (c >= CDIM) {   // zero padding rows (masked in epilogue)
        ((unsigned*)g_wq4)[(size_t)c * 128 + tid] = 0u;
        if (tid == 0) g_sw[c] = 0.0f;
        return;
    }
    float4 v = ((const float4*)(wt + (size_t)c * DDIM))[tid];
    float ss = v.x*v.x + v.y*v.y + v.z*v.z + v.w*v.w;
    #pragma unroll
    for (int o = 16; o; o >>= 1) ss += __shfl_xor_sync(0xffffffffu, ss, o);
    __shared__ float sm[4], sm2[4];
    if ((tid & 31) == 0) sm[tid >> 5] = ss;
    __syncthreads();
    float tot = sm[0] + sm[1] + sm[2] + sm[3];
    float r = 1.0f / fmaxf(sqrtf(tot), 1e-12f);
    float4 n = make_float4(v.x*r, v.y*r, v.z*r, v.w*r);
    float mx = fmaxf(fmaxf(fabsf(n.x), fabsf(n.y)), fmaxf(fabsf(n.z), fabsf(n.w)));
    #pragma unroll
    for (int o = 16; o; o >>= 1) mx = fmaxf(mx, __shfl_xor_sync(0xffffffffu, mx, o));
    if ((tid & 31) == 0) sm2[tid >> 5] = mx;
    __syncthreads();
    mx = fmaxf(fmaxf(sm2[0], sm2[1]), fmaxf(sm2[2], sm2[3]));
    mx = fmaxf(mx, 1e-30f);
    float inv_s = 127.0f / mx;
    ((unsigned*)g_wq4)[(size_t)c * 128 + tid] = pack_s8(n.x, n.y, n.z, n.w, inv_s);
    if (tid == 0) g_sw[c] = mx / 127.0f;
}

__global__ void __launch_bounds__(128) cosgt_kernel(const void* __restrict__ gt,
                                                    const float* __restrict__ wt) {
    int b = blockIdx.x, tid = threadIdx.x;
    long long c = g_is64 ? ((const long long*)gt)[b] : (long long)((const int*)gt)[b];
    float4 w  = ((const float4*)(wt + (size_t)c * DDIM))[tid];
    float4 xn = ((const float4*)(g_xn + (size_t)b * DDIM))[tid];
    float ss = w.x*w.x + w.y*w.y + w.z*w.z + w.w*w.w;
    float dp = w.x*xn.x + w.y*xn.y + w.z*xn.z + w.w*xn.w;
    #pragma unroll
    for (int o = 16; o; o >>= 1) {
        ss += __shfl_xor_sync(0xffffffffu, ss, o);
        dp += __shfl_xor_sync(0xffffffffu, dp, o);
    }
    __shared__ float sms[4], smd[4];
    if ((tid & 31) == 0) { sms[tid >> 5] = ss; smd[tid >> 5] = dp; }
    __syncthreads();
    if (tid == 0) {
        float tss = sms[0] + sms[1] + sms[2] + sms[3];
        float tdp = smd[0] + smd[1] + smd[2] + smd[3];
        g_cosgt[b] = tdp / fmaxf(sqrtf(tss), 1e-12f);
    }
}

// ---------------- IMMA GEMM + fused softmax partials ----------------
// grid (37, 4), 512 threads, 16 warps (4m x 4n), warp tile 32x32, s8 k32 MMA.
__global__ void __launch_bounds__(512, 1) gemm_softmax_kernel() {
    extern __shared__ char smem[];
    unsigned sbA = smem_u32(smem);
    unsigned sbB = sbA + A_SMEM_BYTES;

    int tid  = threadIdx.x;
    int lane = tid & 31;
    int warp = tid >> 5;
    int wm = warp >> 2;       // 0..3
    int wn = warp & 3;        // 0..3
    int m0 = blockIdx.y * 128;
    int bx = blockIdx.x;

    const char* wq = (const char*)g_wq4;
    const char* xq = (const char*)g_xq4;

    int seg = tid & 3;        // 16B segment within 64B chunk-row
    int lrow = tid >> 2;      // row 0..127
    int ntiles = (NT - bx + GRIDX - 1) / GRIDX;
    int nchunks = ntiles * 8;

    // ---- issue B chunks 0..2 into stages 0..2 (1 x 16B per thread) ----
    #pragma unroll
    for (int c0 = 0; c0 < 3; c0++) {
        const char* src = wq + (size_t)(bx * TILE_N + lrow) * 512 + c0 * 64 + seg * 16;
        CP_ASYNC16(sbB + c0 * B_STAGE_BYTES + lrow * BQ_STRIDE + seg * 16, src);
        CP_COMMIT();
    }

    // ---- stage A[128 x 512B] into SMEM (once) ----
    #pragma unroll
    for (int it = 0; it < 8; it++) {
        int idx = it * 512 + tid;
        int r = idx >> 5, s = idx & 31;
        uint4 v = *(const uint4*)(xq + (size_t)(m0 + r) * 512 + s * 16);
        *(uint4*)(smem + r * AQ_STRIDE + s * 16) = v;
    }

    int g4 = lane >> 2, t4 = lane & 3;
    int aRow  = wm * 32 + (lane & 15);
    int aColB = (lane >> 4) << 4;                       // byte offset
    int bRow  = wn * 32 + (lane & 7) + ((lane >> 4) << 3);
    int bColB = ((lane >> 3) & 1) << 4;                 // byte offset

    // row dequant factors (invariant across tiles)
    float fxv[4];
    #pragma unroll
    for (int i = 0; i < 2; i++)
        #pragma unroll
        for (int h = 0; h < 2; h++)
            fxv[i * 2 + h] = SCALE_F * g_sx[m0 + wm * 32 + i * 16 + h * 8 + g4];

    int c = 0;   // global chunk index
    #pragma unroll 1
    for (int t = 0; t < ntiles; t++) {
        int nt = bx + t * GRIDX;
        int acc[2][4][4];
        #pragma unroll
        for (int i = 0; i < 2; i++)
            #pragma unroll
            for (int j = 0; j < 4; j++)
                #pragma unroll
                for (int e = 0; e < 4; e++) acc[i][j][e] = 0;

        #pragma unroll 1
        for (int ck = 0; ck < 8; ck++, c++) {
            CP_WAIT2();                 // chunk c resident
            __syncthreads();            // stage (c+3)&3 fully consumed by all warps

            // issue chunk c+3 into stage (c+3)&3 (may cross tile boundary)
            {
                int cn = c + 3;
                if (cn < nchunks) {
                    int nt2 = bx + (cn >> 3) * GRIDX;
                    int ck2 = cn & 7;
                    const char* src = wq + (size_t)(nt2 * TILE_N + lrow) * 512
                                      + ck2 * 64 + seg * 16;
                    CP_ASYNC16(sbB + (cn & 3) * B_STAGE_BYTES + lrow * BQ_STRIDE + seg * 16, src);
                }
                CP_COMMIT();            // empty group keeps the count aligned at tail
            }

            // ---- consume stage c&3: 2 k32 steps, frag double-buffered ----
            unsigned bB = sbB + (c & 3) * B_STAGE_BYTES;
            unsigned a[2][2][4], bf[2][4][2];

            load_frags8(sbA, bB, aRow, aColB, bRow, bColB, 0, a[0], bf[0]);
            #pragma unroll
            for (int ks = 0; ks < 2; ks++) {
                int cur = ks & 1;
                if (ks < 1)
                    load_frags8(sbA, bB, aRow, aColB, bRow, bColB, 32,
                                a[cur ^ 1], bf[cur ^ 1]);
                #pragma unroll
                for (int i = 0; i < 2; i++)
                    #pragma unroll
                    for (int j = 0; j < 4; j++)
                        asm volatile(
                            "mma.sync.aligned.m16n8k32.row.col.s32.s8.s8.s32 "
                            "{%0,%1,%2,%3},{%4,%5,%6,%7},{%8,%9},{%0,%1,%2,%3};"
                            : "+r"(acc[i][j][0]), "+r"(acc[i][j][1]),
                              "+r"(acc[i][j][2]), "+r"(acc[i][j][3])
                            : "r"(a[cur][i][0]), "r"(a[cur][i][1]),
                              "r"(a[cur][i][2]), "r"(a[cur][i][3]),
                              "r"(bf[cur][j][0]), "r"(bf[cur][j][1]));
            }
        }

        // ---- per-warp epilogue over this warp's 32 cols ----
        int n0 = nt * TILE_N;
        float swv[8];
        #pragma unroll
        for (int j = 0; j < 4; j++)
            #pragma unroll
            for (int e2 = 0; e2 < 2; e2++)
                swv[j * 2 + e2] = g_sw[n0 + wn * 32 + j * 8 + t4 * 2 + e2];

        #pragma unroll
        for (int i = 0; i < 2; i++) {
            #pragma unroll
            for (int h = 0; h < 2; h++) {
                float fx = fxv[i * 2 + h];
                float m = -INFINITY;
                float z[8];
                #pragma unroll
                for (int j = 0; j < 4; j++) {
                    #pragma unroll
                    for (int e2 = 0; e2 < 2; e2++) {
                        int gc = n0 + wn * 32 + j * 8 + t4 * 2 + e2;
                        float v = fx * swv[j * 2 + e2] * (float)acc[i][j][h * 2 + e2];
                        z[j * 2 + e2] = (gc < CDIM) ? v : -INFINITY;
                        m = fmaxf(m, z[j * 2 + e2]);
                    }
                }
                m = fmaxf(m, __shfl_xor_sync(0xffffffffu, m, 1));
                m = fmaxf(m, __shfl_xor_sync(0xffffffffu, m, 2));
                float s = 0.0f;
                if (m > -1e37f) {
                    #pragma unroll
                    for (int j8 = 0; j8 < 8; j8++) s += __expf(z[j8] - m);
                }
                s += __shfl_xor_sync(0xffffffffu, s, 1);
                s += __shfl_xor_sync(0xffffffffu, s, 2);
                if (t4 == 0) {
                    int r = m0 + wm * 32 + i * 16 + h * 8 + g4;
                    size_t idx = (size_t)r * NPART + nt * 4 + wn;
                    g_pm[idx] = fmaxf(m, -3.0e38f);   // finite sentinel: NaN-safe merge
                    g_ps[idx] = s;
                }
            }
        }
    }
}

// ---------------- logsumexp merge + margin + NLL ----------------
__global__ void __launch_bounds__(256) reduce_kernel() {
    int b = blockIdx.x, tid = threadIdx.x;
    float M = -INFINITY, S = 0.0f;
    for (int i = tid; i < NPART; i += 256) {
        float m = g_pm[(size_t)b * NPART + i];
        float s = g_ps[(size_t)b * NPART + i];
        if (m > M) { S = S * __expf(M - m) + s; M = m; }
        else       { S += s * __expf(m - M); }
    }
    __shared__ float sm[256], ss[256];
    sm[tid] = M; ss[tid] = S;
    __syncthreads();
    for (int o = 128; o; o >>= 1) {
        if (tid < o) {
            float m2 = sm[tid + o], s2 = ss[tid + o];
            float m1 = sm[tid],     s1 = ss[tid];
            float mn = fmaxf(m1, m2);
            sm[tid] = mn;
            ss[tid] = s1 * __expf(m1 - mn) + s2 * __expf(m2 - mn);
        }
        __syncthreads();
    }
    if (tid == 0) {
        float Mf = sm[0], Sf = ss[0];
        float zg = SCALE_F * g_cosgt[b];
        float zm = zg - SCALE_F * MARGIN_F;
        // swap the gt term: remove (approx) unmargined, add exact margined
        Sf = Sf - expf(zg - Mf) + expf(zm - Mf);
        float lse = Mf + logf(Sf);
        g_nll[b] = lse - zm;
    }
}

__global__ void __launch_bounds__(512) mean_kernel(float* __restrict__ out) {
    __shared__ float sm[512];
    int t = threadIdx.x;
    sm[t] = g_nll[t];
    __syncthreads();
    for (int o = 256; o; o >>= 1) {
        if (t < o) sm[t] += sm[t + o];
        __syncthreads();
    }
    if (t == 0) out[0] = sm[0] * (1.0f / (float)BDIM);
}

// ---------------- launch ----------------
extern "C" void kernel_launch(void* const* d_in, const int* in_sizes, int n_in,
                              void* d_out, int out_size) {
    const float* x  = (const float*)d_in[0];
    const void*  gt = d_in[1];
    const float* wt = (const float*)d_in[2];
    float* out = (float*)d_out;

    static int smem_set = 0;
    if (!smem_set) {
        cudaFuncSetAttribute(gemm_softmax_kernel,
                             cudaFuncAttributeMaxDynamicSharedMemorySize, SMEM_DYN);
        smem_set = 1;
    }

    detect_gt_kernel<<<1, 512>>>((const int*)gt);
    norm_x_kernel<<<BDIM, 128>>>(x);
    norm_w_kernel<<<C_PAD, 128>>>(wt);
    cosgt_kernel<<<BDIM, 128>>>(gt, wt);
    gemm_softmax_kernel<<<dim3(GRIDX, 4), 512, SMEM_DYN>>>();
    reduce_kernel<<<BDIM, 256>>>();
    mean_kernel<<<1, 512>>>(out);
}